// round 2
// baseline (speedup 1.0000x reference)
#include <cuda_runtime.h>
#include <math.h>

// Problem constants (match reference)
#define T      512
#define HDIM   2048
#define NE     32
#define TOPK   8
#define IDIM   1408
#define NGRP   8
#define TKG    4
#define CAP    256          // 2*T*K/E
#define RSF    2.5f
#define ISH    2816         // I * NS (shared experts intermediate)

// ---------------- device scratch (static; no allocations) ----------------
__device__ int   g_topk_ids[T * TOPK];
__device__ float g_topk_w[T * TOPK];
__device__ int   g_assign_slot[T * TOPK];   // slot index or -1 (dropped)
__device__ int   g_slot_token[NE * CAP];
__device__ int   g_counts[NE];
__device__ float g_h1[NE * CAP * IDIM];     // routed silu(gate)*up, 46 MB
__device__ float g_y [NE * CAP * HDIM];     // routed expert out,   67 MB
__device__ float g_hs[T * ISH];             // shared silu*up,      5.8 MB

// Buffer selectors resolved in DEVICE code (passing __device__ symbols as
// host-side kernel args is invalid — host shadow address, silently wrong
// under ATS).
#define PTR_PARAM 0
#define PTR_H1    1
#define PTR_Y     2
#define PTR_HS    3

template <int M>
__device__ __forceinline__ float* resolve(float* p) {
    if constexpr (M == PTR_H1) return g_h1;
    else if constexpr (M == PTR_Y) return g_y;
    else if constexpr (M == PTR_HS) return g_hs;
    else return p;
}

// ---------------- routing: noaux_tc grouped top-k ----------------
__global__ void routing_kernel(const float* __restrict__ x,
                               const float* __restrict__ gw,
                               const float* __restrict__ bias) {
    int t    = blockIdx.x;
    int tid  = threadIdx.x;       // 256 threads
    int lane = tid & 31;
    int wid  = tid >> 5;          // 8 warps: partial dot products

    __shared__ float part[8][32];
    const float* xr = x + (long long)t * HDIM;
    float acc = 0.f;
    int h0 = wid * (HDIM / 8);
    for (int h = h0; h < h0 + HDIM / 8; ++h)
        acc += xr[h] * gw[h * NE + lane];
    part[wid][lane] = acc;
    __syncthreads();

    if (wid != 0) return;

    float logit = 0.f;
#pragma unroll
    for (int w = 0; w < 8; ++w) logit += part[w][lane];

    float s  = 1.f / (1.f + expf(-logit));   // unbiased sigmoid score
    float sb = s + bias[lane];               // biased score for selection

    // --- per-group (4 experts/group) sum of top-2 of sb ---
    float p   = __shfl_xor_sync(0xffffffffu, sb, 1);
    float hi  = fmaxf(sb, p), lo = fminf(sb, p);
    float hi2 = __shfl_xor_sync(0xffffffffu, hi, 2);
    float lo2 = __shfl_xor_sync(0xffffffffu, lo, 2);
    float gs  = (hi >= hi2) ? hi + fmaxf(hi2, lo) : hi2 + fmaxf(hi, lo2);

    // --- select top-4 groups (tie -> lower index, as in lax.top_k) ---
    int g = lane >> 2;
    int grank = 0;
#pragma unroll
    for (int g2 = 0; g2 < NGRP; ++g2) {
        float og = __shfl_sync(0xffffffffu, gs, g2 * 4);
        if (og > gs || (og == gs && g2 < g)) ++grank;
    }
    float cand = (grank < TKG) ? sb : -INFINITY;

    // --- iterative top-8 over masked biased scores (descending order) ---
    float v = cand;
    int   sel_e = 0; float sel_w = 0.f;
#pragma unroll
    for (int k = 0; k < TOPK; ++k) {
        float bv = v; int bi = lane;
#pragma unroll
        for (int off = 16; off; off >>= 1) {
            float ov = __shfl_xor_sync(0xffffffffu, bv, off);
            int   oi = __shfl_xor_sync(0xffffffffu, bi, off);
            if (ov > bv || (ov == bv && oi < bi)) { bv = ov; bi = oi; }
        }
        float ws = __shfl_sync(0xffffffffu, s, bi);  // weight from UNBIASED score
        if (lane == k)  { sel_e = bi; sel_w = ws; }
        if (lane == bi) v = -INFINITY;
    }

    // --- renormalize * RSF ---
    float wv = (lane < TOPK) ? sel_w : 0.f;
#pragma unroll
    for (int off = 16; off; off >>= 1) wv += __shfl_xor_sync(0xffffffffu, wv, off);
    if (lane < TOPK) {
        g_topk_ids[t * TOPK + lane] = sel_e;
        g_topk_w  [t * TOPK + lane] = sel_w / wv * RSF;
    }
}

// ---------------- deterministic capacity ranking (cumsum order) ----------------
__global__ void rank_kernel() {
    int w    = threadIdx.x >> 5;   // expert id, 32 warps
    int lane = threadIdx.x & 31;
    int cnt  = 0;
    for (int i0 = 0; i0 < T * TOPK; i0 += 32) {
        int i = i0 + lane;
        int e = g_topk_ids[i];
        bool m = (e == w);
        unsigned mask = __ballot_sync(0xffffffffu, m);
        if (m) {
            int r = cnt + __popc(mask & ((1u << lane) - 1u));
            if (r < CAP) {
                g_assign_slot[i] = w * CAP + r;
                g_slot_token[w * CAP + r] = i >> 3;   // token = i / TOPK
            } else {
                g_assign_slot[i] = -1;                // dropped (over capacity)
            }
        }
        cnt += __popc(mask);
    }
    if (lane == 0) g_counts[w] = min(cnt, CAP);
}

// ---------------- generic 64x64 fp32 tiled GEMM ----------------
// FUSED: C = silu(A*B[:, n]) * (A*B[:, n+up_off])
// GROUPED: per-expert (blockIdx.z), M = counts[e]
// GATHER: A rows indirected through slot_token (A is the token matrix X)
// AM/CM: device-side buffer selection for A and C
template <bool FUSED, bool GROUPED, bool GATHER, int AM, int CM>
__global__ void sgemm64(const float* __restrict__ Ain, int lda, long long a_estride,
                        const float* __restrict__ B, int ldb, long long b_estride, int up_off,
                        float* __restrict__ Cin, int ldc, long long c_estride,
                        int M, int Kd) {
    const float* A = resolve<AM>(const_cast<float*>(Ain));
    float*       Cm = resolve<CM>(Cin);

    const int tid = threadIdx.x;      // 256 threads
    const int e   = GROUPED ? blockIdx.z : 0;
    const int Mloc = GROUPED ? g_counts[e] : M;
    const int m0 = blockIdx.y * 64;
    if (m0 >= Mloc) return;
    const int n0 = blockIdx.x * 64;

    const float* Bp = B + (GROUPED ? (long long)e * b_estride : 0ll);
    float*       Cp = Cm + (GROUPED ? (long long)e * c_estride : 0ll);
    const float* Ap = A + ((GROUPED && !GATHER) ? (long long)e * a_estride : 0ll);

    __shared__ float As[16][64];
    __shared__ float Bs[16][64];
    __shared__ float Bs2[FUSED ? 16 : 1][FUSED ? 64 : 1];

    // per-thread A-row pointers
    const float* arow[4];
    bool avalid[4];
#pragma unroll
    for (int l = 0; l < 4; ++l) {
        int idx = tid + 256 * l;
        int m   = idx >> 4;
        int gm  = m0 + m;
        bool vld = gm < Mloc;
        int row;
        if (GATHER) row = vld ? g_slot_token[e * CAP + gm] : 0;
        else        row = vld ? gm : 0;
        arow[l]  = Ap + (long long)row * lda;
        avalid[l] = vld;
    }

    float acc[4][4];
    float acc2[FUSED ? 4 : 1][FUSED ? 4 : 1];
#pragma unroll
    for (int i = 0; i < 4; ++i)
#pragma unroll
        for (int j = 0; j < 4; ++j) {
            acc[i][j] = 0.f;
            if (FUSED) acc2[i][j] = 0.f;
        }

    const int ty = tid >> 4, tx = tid & 15;

    for (int k0 = 0; k0 < Kd; k0 += 16) {
#pragma unroll
        for (int l = 0; l < 4; ++l) {
            int idx = tid + 256 * l;
            int m = idx >> 4, kk = idx & 15;
            As[kk][m] = avalid[l] ? arow[l][k0 + kk] : 0.f;
        }
#pragma unroll
        for (int l = 0; l < 4; ++l) {
            int idx = tid + 256 * l;
            int kk = idx >> 6, n = idx & 63;
            long long boff = (long long)(k0 + kk) * ldb + n0 + n;
            Bs[kk][n] = Bp[boff];
            if (FUSED) Bs2[kk][n] = Bp[boff + up_off];
        }
        __syncthreads();
#pragma unroll
        for (int kk = 0; kk < 16; ++kk) {
            float a[4], b[4], b2[FUSED ? 4 : 1];
#pragma unroll
            for (int i = 0; i < 4; ++i) a[i] = As[kk][(ty << 2) + i];
#pragma unroll
            for (int j = 0; j < 4; ++j) {
                b[j] = Bs[kk][(tx << 2) + j];
                if (FUSED) b2[j] = Bs2[kk][(tx << 2) + j];
            }
#pragma unroll
            for (int i = 0; i < 4; ++i)
#pragma unroll
                for (int j = 0; j < 4; ++j) {
                    acc[i][j] += a[i] * b[j];
                    if (FUSED) acc2[i][j] += a[i] * b2[j];
                }
        }
        __syncthreads();
    }

#pragma unroll
    for (int i = 0; i < 4; ++i) {
        int gm = m0 + (ty << 2) + i;
        if (gm >= Mloc) continue;
#pragma unroll
        for (int j = 0; j < 4; ++j) {
            int gn = n0 + (tx << 2) + j;
            float val;
            if (FUSED) {
                float gx = acc[i][j], ux = acc2[i][j];
                val = (gx / (1.f + expf(-gx))) * ux;   // silu(g) * u
            } else {
                val = acc[i][j];
            }
            Cp[(long long)gm * ldc + gn] = val;
        }
    }
}

// ---------------- combine: out (already = shared) += sum_k w_k * y[slot_k] ----------------
__global__ void combine_kernel(float* __restrict__ out) {
    int t = blockIdx.x;
    __shared__ int   sslot[TOPK];
    __shared__ float sw[TOPK];
    if (threadIdx.x < TOPK) {
        sslot[threadIdx.x] = g_assign_slot[t * TOPK + threadIdx.x];
        sw[threadIdx.x]    = g_topk_w[t * TOPK + threadIdx.x];
    }
    __syncthreads();
    for (int h = threadIdx.x; h < HDIM; h += 256) {
        float acc = out[(long long)t * HDIM + h];
#pragma unroll
        for (int k = 0; k < TOPK; ++k) {
            int sl = sslot[k];
            if (sl >= 0) acc += sw[k] * g_y[(long long)sl * HDIM + h];
        }
        out[(long long)t * HDIM + h] = acc;
    }
}

// ---------------- launch ----------------
extern "C" void kernel_launch(void* const* d_in, const int* in_sizes, int n_in,
                              void* d_out, int out_size) {
    const float* x     = (const float*)d_in[0];   // hidden_states [512,2048]
    // d_in[1] = residual (unused by reference output)
    const float* gw    = (const float*)d_in[2];   // gate_w [2048,32]
    const float* bias  = (const float*)d_in[3];   // bias [32]
    const float* w13   = (const float*)d_in[4];   // [32,2048,2816]
    const float* w2    = (const float*)d_in[5];   // [32,1408,2048]
    const float* sgu   = (const float*)d_in[6];   // [2048,5632]
    const float* sdn   = (const float*)d_in[7];   // [2816,2048]
    float* out = (float*)d_out;

    // 1) routing
    routing_kernel<<<T, 256>>>(x, gw, bias);
    // 2) capacity ranking
    rank_kernel<<<1, 1024>>>();
    // 3) routed gemm1 (gathered X @ w13, fused silu*up) -> g_h1 [E*CAP, IDIM]
    sgemm64<true, true, true, PTR_PARAM, PTR_H1><<<dim3(IDIM / 64, CAP / 64, NE), 256>>>(
        x, HDIM, 0ll,
        w13, 2 * IDIM, (long long)HDIM * 2 * IDIM, IDIM,
        nullptr, IDIM, (long long)CAP * IDIM,
        CAP, HDIM);
    // 4) routed gemm2 (g_h1 @ w2) -> g_y [E*CAP, HDIM]
    sgemm64<false, true, false, PTR_H1, PTR_Y><<<dim3(HDIM / 64, CAP / 64, NE), 256>>>(
        nullptr, IDIM, (long long)CAP * IDIM,
        w2, HDIM, (long long)IDIM * HDIM, 0,
        nullptr, HDIM, (long long)CAP * HDIM,
        CAP, IDIM);
    // 5) shared gemm1 (X @ shared_gate_up, fused silu*up) -> g_hs [T, ISH]
    sgemm64<true, false, false, PTR_PARAM, PTR_HS><<<dim3(ISH / 64, T / 64, 1), 256>>>(
        x, HDIM, 0ll,
        sgu, 2 * ISH, 0ll, ISH,
        nullptr, ISH, 0ll,
        T, HDIM);
    // 6) shared gemm2 (g_hs @ shared_down) -> out [T, HDIM]
    sgemm64<false, false, false, PTR_HS, PTR_PARAM><<<dim3(HDIM / 64, T / 64, 1), 256>>>(
        nullptr, ISH, 0ll,
        sdn, HDIM, 0ll, 0,
        out, HDIM, 0ll,
        T, ISH);
    // 7) combine routed into out
    combine_kernel<<<T, 256>>>(out);
}

// round 3
// speedup vs baseline: 2.8730x; 2.8730x over previous
#include <cuda_runtime.h>
#include <math.h>

// Problem constants (match reference)
#define T      512
#define HDIM   2048
#define NE     32
#define TOPK   8
#define IDIM   1408
#define NGRP   8
#define TKG    4
#define CAP    256          // 2*T*K/E
#define RSF    2.5f
#define ISH    2816         // I * NS (shared experts intermediate)

// ---------------- device scratch (static; no allocations) ----------------
__device__ int   g_topk_ids[T * TOPK];
__device__ float g_topk_w[T * TOPK];
__device__ int   g_assign_slot[T * TOPK];   // slot index or -1 (dropped)
__device__ int   g_slot_token[NE * CAP];
__device__ int   g_counts[NE];
__device__ float g_h1[NE * CAP * IDIM];     // routed silu(gate)*up
__device__ float g_y [NE * CAP * HDIM];     // routed expert out
__device__ float g_hs[T * ISH];             // shared silu*up

// Buffer selectors resolved in DEVICE code (host cannot pass __device__ symbols)
#define PTR_PARAM 0
#define PTR_H1    1
#define PTR_Y     2
#define PTR_HS    3

template <int M>
__device__ __forceinline__ float* resolve(float* p) {
    if constexpr (M == PTR_H1) return g_h1;
    else if constexpr (M == PTR_Y) return g_y;
    else if constexpr (M == PTR_HS) return g_hs;
    else return p;
}

// ---------------- tf32 helpers ----------------
__device__ __forceinline__ unsigned f2tf(float f) {
    unsigned r; asm("cvt.rna.tf32.f32 %0, %1;" : "=r"(r) : "f"(f)); return r;
}
__device__ __forceinline__ void mma_tf32(float* c, const unsigned* a, unsigned b0, unsigned b1) {
    asm("mma.sync.aligned.m16n8k8.row.col.f32.tf32.tf32.f32 "
        "{%0,%1,%2,%3},{%4,%5,%6,%7},{%8,%9},{%0,%1,%2,%3};"
        : "+f"(c[0]), "+f"(c[1]), "+f"(c[2]), "+f"(c[3])
        : "r"(a[0]), "r"(a[1]), "r"(a[2]), "r"(a[3]), "r"(b0), "r"(b1));
}
__device__ __forceinline__ float silu_mul(float g, float u) {
    return (g / (1.f + expf(-g))) * u;
}

// ---------------- routing: noaux_tc grouped top-k ----------------
__global__ void routing_kernel(const float* __restrict__ x,
                               const float* __restrict__ gw,
                               const float* __restrict__ bias) {
    int t    = blockIdx.x;
    int tid  = threadIdx.x;       // 256 threads
    int lane = tid & 31;
    int wid  = tid >> 5;          // 8 warps: partial dot products

    __shared__ float part[8][32];
    const float* xr = x + (long long)t * HDIM;
    float acc = 0.f;
    int h0 = wid * (HDIM / 8);
    for (int h = h0; h < h0 + HDIM / 8; ++h)
        acc += xr[h] * gw[h * NE + lane];
    part[wid][lane] = acc;
    __syncthreads();

    if (wid != 0) return;

    float logit = 0.f;
#pragma unroll
    for (int w = 0; w < 8; ++w) logit += part[w][lane];

    float s  = 1.f / (1.f + expf(-logit));   // unbiased sigmoid score
    float sb = s + bias[lane];               // biased score for selection

    // per-group (4 experts/group) sum of top-2 of sb
    float p   = __shfl_xor_sync(0xffffffffu, sb, 1);
    float hi  = fmaxf(sb, p), lo = fminf(sb, p);
    float hi2 = __shfl_xor_sync(0xffffffffu, hi, 2);
    float lo2 = __shfl_xor_sync(0xffffffffu, lo, 2);
    float gs  = (hi >= hi2) ? hi + fmaxf(hi2, lo) : hi2 + fmaxf(hi, lo2);

    // select top-4 groups (tie -> lower index)
    int g = lane >> 2;
    int grank = 0;
#pragma unroll
    for (int g2 = 0; g2 < NGRP; ++g2) {
        float og = __shfl_sync(0xffffffffu, gs, g2 * 4);
        if (og > gs || (og == gs && g2 < g)) ++grank;
    }
    float cand = (grank < TKG) ? sb : -INFINITY;

    // iterative top-8 over masked biased scores
    float v = cand;
    int   sel_e = 0; float sel_w = 0.f;
#pragma unroll
    for (int k = 0; k < TOPK; ++k) {
        float bv = v; int bi = lane;
#pragma unroll
        for (int off = 16; off; off >>= 1) {
            float ov = __shfl_xor_sync(0xffffffffu, bv, off);
            int   oi = __shfl_xor_sync(0xffffffffu, bi, off);
            if (ov > bv || (ov == bv && oi < bi)) { bv = ov; bi = oi; }
        }
        float ws = __shfl_sync(0xffffffffu, s, bi);
        if (lane == k)  { sel_e = bi; sel_w = ws; }
        if (lane == bi) v = -INFINITY;
    }

    float wv = (lane < TOPK) ? sel_w : 0.f;
#pragma unroll
    for (int off = 16; off; off >>= 1) wv += __shfl_xor_sync(0xffffffffu, wv, off);
    if (lane < TOPK) {
        g_topk_ids[t * TOPK + lane] = sel_e;
        g_topk_w  [t * TOPK + lane] = sel_w / wv * RSF;
    }
}

// ---------------- deterministic capacity ranking (cumsum order) ----------------
__global__ void rank_kernel() {
    int w    = threadIdx.x >> 5;   // expert id, 32 warps
    int lane = threadIdx.x & 31;
    int cnt  = 0;
    for (int i0 = 0; i0 < T * TOPK; i0 += 32) {
        int i = i0 + lane;
        int e = g_topk_ids[i];
        bool m = (e == w);
        unsigned mask = __ballot_sync(0xffffffffu, m);
        if (m) {
            int r = cnt + __popc(mask & ((1u << lane) - 1u));
            if (r < CAP) {
                g_assign_slot[i] = w * CAP + r;
                g_slot_token[w * CAP + r] = i >> 3;
            } else {
                g_assign_slot[i] = -1;
            }
        }
        cnt += __popc(mask);
    }
    if (lane == 0) g_counts[w] = min(cnt, CAP);
}

// ============================================================================
// Fused gate/up tf32 tensor-core GEMM: C = silu(A@Bg) * (A@Bu)
// Block tile: M=128, N=64 (gate cols [n0,n0+64) and up cols [n0+up_off,...)).
// 8 warps in 4(m) x 2(n): warp tile 32x32. mma m16n8k8 tf32.
// ============================================================================
template <bool GATHER, bool GROUPED, int AM, int CM>
__global__ void __launch_bounds__(256)
gemm_fused(const float* __restrict__ Ain, int lda,
           const float* __restrict__ B, int ldb, int up_off, long long b_estride,
           float* __restrict__ Cin, int ldc, long long c_estride,
           int M, int Kd) {
    const float* A  = resolve<AM>(const_cast<float*>(Ain));
    float*       Cm = resolve<CM>(Cin);

    const int e    = GROUPED ? blockIdx.z : 0;
    const int Mloc = GROUPED ? g_counts[e] : M;
    const int m0   = blockIdx.y * 128;
    if (m0 >= Mloc) return;
    const int n0   = blockIdx.x * 64;

    const float* Bp = B + (GROUPED ? (long long)e * b_estride : 0ll);
    float*       Cp = Cm + (GROUPED ? (long long)e * c_estride : 0ll);

    __shared__ unsigned As[16][132];
    __shared__ unsigned Bg[16][68];
    __shared__ unsigned Bu[16][68];

    const int tid  = threadIdx.x;
    const int lane = tid & 31;
    const int wid  = tid >> 5;
    const int gid  = lane >> 2;
    const int tig  = lane & 3;
    const int m_w  = (wid >> 1) * 32;
    const int n_w  = (wid & 1) * 32;

    // A load mapping: rows r0, r0+64; k-quad k4
    const int r0 = tid >> 2;
    const int k4 = (tid & 3) * 4;
    const int gm0 = m0 + r0, gm1 = m0 + r0 + 64;
    const bool av0 = gm0 < Mloc, av1 = gm1 < Mloc;
    int row0, row1;
    if (GATHER) {
        row0 = av0 ? g_slot_token[e * CAP + gm0] : 0;
        row1 = av1 ? g_slot_token[e * CAP + gm1] : 0;
    } else {
        row0 = av0 ? gm0 : 0;
        row1 = av1 ? gm1 : 0;
    }
    const float* ap0 = A + (long long)row0 * lda + k4;
    const float* ap1 = A + (long long)row1 * lda + k4;

    // B load mapping: row bk, 4 cols bn4
    const int bk  = tid >> 4;
    const int bn4 = (tid & 15) * 4;
    const float* bgp = Bp + (long long)bk * ldb + n0 + bn4;
    const float* bup = bgp + up_off;

    float accg[2][4][4], accu[2][4][4];
#pragma unroll
    for (int mi = 0; mi < 2; ++mi)
#pragma unroll
        for (int ni = 0; ni < 4; ++ni)
#pragma unroll
            for (int r = 0; r < 4; ++r) { accg[mi][ni][r] = 0.f; accu[mi][ni][r] = 0.f; }

    float4 ra0, ra1, rbg, rbu;
    const float4 fz = make_float4(0.f, 0.f, 0.f, 0.f);
    ra0 = av0 ? *(const float4*)(ap0) : fz;
    ra1 = av1 ? *(const float4*)(ap1) : fz;
    rbg = *(const float4*)(bgp);
    rbu = *(const float4*)(bup);

    for (int k0 = 0; k0 < Kd; k0 += 16) {
        // stage to SMEM with rne tf32 conversion
        As[k4 + 0][r0] = f2tf(ra0.x); As[k4 + 1][r0] = f2tf(ra0.y);
        As[k4 + 2][r0] = f2tf(ra0.z); As[k4 + 3][r0] = f2tf(ra0.w);
        As[k4 + 0][r0 + 64] = f2tf(ra1.x); As[k4 + 1][r0 + 64] = f2tf(ra1.y);
        As[k4 + 2][r0 + 64] = f2tf(ra1.z); As[k4 + 3][r0 + 64] = f2tf(ra1.w);
        Bg[bk][bn4 + 0] = f2tf(rbg.x); Bg[bk][bn4 + 1] = f2tf(rbg.y);
        Bg[bk][bn4 + 2] = f2tf(rbg.z); Bg[bk][bn4 + 3] = f2tf(rbg.w);
        Bu[bk][bn4 + 0] = f2tf(rbu.x); Bu[bk][bn4 + 1] = f2tf(rbu.y);
        Bu[bk][bn4 + 2] = f2tf(rbu.z); Bu[bk][bn4 + 3] = f2tf(rbu.w);
        __syncthreads();

        if (k0 + 16 < Kd) {
            ra0 = av0 ? *(const float4*)(ap0 + k0 + 16) : fz;
            ra1 = av1 ? *(const float4*)(ap1 + k0 + 16) : fz;
            rbg = *(const float4*)(bgp + (long long)(k0 + 16) * ldb);
            rbu = *(const float4*)(bup + (long long)(k0 + 16) * ldb);
        }

#pragma unroll
        for (int ks = 0; ks < 16; ks += 8) {
            unsigned a[2][4];
#pragma unroll
            for (int mi = 0; mi < 2; ++mi) {
                int mc = m_w + 16 * mi + gid;
                a[mi][0] = As[ks + tig][mc];
                a[mi][1] = As[ks + tig][mc + 8];
                a[mi][2] = As[ks + tig + 4][mc];
                a[mi][3] = As[ks + tig + 4][mc + 8];
            }
#pragma unroll
            for (int ni = 0; ni < 4; ++ni) {
                int nc = n_w + 8 * ni + gid;
                unsigned bg0 = Bg[ks + tig][nc],     bg1 = Bg[ks + tig + 4][nc];
                unsigned bu0 = Bu[ks + tig][nc],     bu1 = Bu[ks + tig + 4][nc];
#pragma unroll
                for (int mi = 0; mi < 2; ++mi) {
                    mma_tf32(accg[mi][ni], a[mi], bg0, bg1);
                    mma_tf32(accu[mi][ni], a[mi], bu0, bu1);
                }
            }
        }
        __syncthreads();
    }

    // epilogue: silu(gate)*up
#pragma unroll
    for (int mi = 0; mi < 2; ++mi) {
        int rA = m0 + m_w + 16 * mi + gid;
        int rB = rA + 8;
#pragma unroll
        for (int ni = 0; ni < 4; ++ni) {
            int c0 = n0 + n_w + 8 * ni + 2 * tig;
            if (rA < Mloc) {
                Cp[(long long)rA * ldc + c0    ] = silu_mul(accg[mi][ni][0], accu[mi][ni][0]);
                Cp[(long long)rA * ldc + c0 + 1] = silu_mul(accg[mi][ni][1], accu[mi][ni][1]);
            }
            if (rB < Mloc) {
                Cp[(long long)rB * ldc + c0    ] = silu_mul(accg[mi][ni][2], accu[mi][ni][2]);
                Cp[(long long)rB * ldc + c0 + 1] = silu_mul(accg[mi][ni][3], accu[mi][ni][3]);
            }
        }
    }
}

// ============================================================================
// Plain tf32 tensor-core GEMM: C = A @ B
// Block tile M=128, N=128. 8 warps 2(m) x 4(n): warp tile 64x32.
// ============================================================================
template <bool GROUPED, int AM, int CM>
__global__ void __launch_bounds__(256)
gemm_plain(const float* __restrict__ Ain, int lda, long long a_estride,
           const float* __restrict__ B, int ldb, long long b_estride,
           float* __restrict__ Cin, int ldc, long long c_estride,
           int M, int Kd) {
    const float* A  = resolve<AM>(const_cast<float*>(Ain));
    float*       Cm = resolve<CM>(Cin);

    const int e    = GROUPED ? blockIdx.z : 0;
    const int Mloc = GROUPED ? g_counts[e] : M;
    const int m0   = blockIdx.y * 128;
    if (m0 >= Mloc) return;
    const int n0   = blockIdx.x * 128;

    const float* Bp = B + (GROUPED ? (long long)e * b_estride : 0ll);
    const float* Ap = A + (GROUPED ? (long long)e * a_estride : 0ll);
    float*       Cp = Cm + (GROUPED ? (long long)e * c_estride : 0ll);

    __shared__ unsigned As[16][132];
    __shared__ unsigned Bs[16][132];

    const int tid  = threadIdx.x;
    const int lane = tid & 31;
    const int wid  = tid >> 5;
    const int gid  = lane >> 2;
    const int tig  = lane & 3;
    const int m_w  = (wid >> 2) * 64;
    const int n_w  = (wid & 3) * 32;

    const int r0 = tid >> 2;
    const int k4 = (tid & 3) * 4;
    const int gm0 = m0 + r0, gm1 = m0 + r0 + 64;
    const bool av0 = gm0 < Mloc, av1 = gm1 < Mloc;
    const float* ap0 = Ap + (long long)(av0 ? gm0 : 0) * lda + k4;
    const float* ap1 = Ap + (long long)(av1 ? gm1 : 0) * lda + k4;

    const int bk  = tid >> 5;           // rows bk, bk+8
    const int bn4 = (tid & 31) * 4;
    const float* bp0 = Bp + (long long)bk * ldb + n0 + bn4;
    const float* bp1 = bp0 + 8ll * ldb;

    float acc[4][4][4];
#pragma unroll
    for (int mi = 0; mi < 4; ++mi)
#pragma unroll
        for (int ni = 0; ni < 4; ++ni)
#pragma unroll
            for (int r = 0; r < 4; ++r) acc[mi][ni][r] = 0.f;

    float4 ra0, ra1, rb0, rb1;
    const float4 fz = make_float4(0.f, 0.f, 0.f, 0.f);
    ra0 = av0 ? *(const float4*)(ap0) : fz;
    ra1 = av1 ? *(const float4*)(ap1) : fz;
    rb0 = *(const float4*)(bp0);
    rb1 = *(const float4*)(bp1);

    for (int k0 = 0; k0 < Kd; k0 += 16) {
        As[k4 + 0][r0] = f2tf(ra0.x); As[k4 + 1][r0] = f2tf(ra0.y);
        As[k4 + 2][r0] = f2tf(ra0.z); As[k4 + 3][r0] = f2tf(ra0.w);
        As[k4 + 0][r0 + 64] = f2tf(ra1.x); As[k4 + 1][r0 + 64] = f2tf(ra1.y);
        As[k4 + 2][r0 + 64] = f2tf(ra1.z); As[k4 + 3][r0 + 64] = f2tf(ra1.w);
        Bs[bk][bn4 + 0] = f2tf(rb0.x); Bs[bk][bn4 + 1] = f2tf(rb0.y);
        Bs[bk][bn4 + 2] = f2tf(rb0.z); Bs[bk][bn4 + 3] = f2tf(rb0.w);
        Bs[bk + 8][bn4 + 0] = f2tf(rb1.x); Bs[bk + 8][bn4 + 1] = f2tf(rb1.y);
        Bs[bk + 8][bn4 + 2] = f2tf(rb1.z); Bs[bk + 8][bn4 + 3] = f2tf(rb1.w);
        __syncthreads();

        if (k0 + 16 < Kd) {
            ra0 = av0 ? *(const float4*)(ap0 + k0 + 16) : fz;
            ra1 = av1 ? *(const float4*)(ap1 + k0 + 16) : fz;
            rb0 = *(const float4*)(bp0 + (long long)(k0 + 16) * ldb);
            rb1 = *(const float4*)(bp1 + (long long)(k0 + 16) * ldb);
        }

#pragma unroll
        for (int ks = 0; ks < 16; ks += 8) {
            unsigned a[4][4];
#pragma unroll
            for (int mi = 0; mi < 4; ++mi) {
                int mc = m_w + 16 * mi + gid;
                a[mi][0] = As[ks + tig][mc];
                a[mi][1] = As[ks + tig][mc + 8];
                a[mi][2] = As[ks + tig + 4][mc];
                a[mi][3] = As[ks + tig + 4][mc + 8];
            }
#pragma unroll
            for (int ni = 0; ni < 4; ++ni) {
                int nc = n_w + 8 * ni + gid;
                unsigned b0 = Bs[ks + tig][nc], b1 = Bs[ks + tig + 4][nc];
#pragma unroll
                for (int mi = 0; mi < 4; ++mi)
                    mma_tf32(acc[mi][ni], a[mi], b0, b1);
            }
        }
        __syncthreads();
    }

#pragma unroll
    for (int mi = 0; mi < 4; ++mi) {
        int rA = m0 + m_w + 16 * mi + gid;
        int rB = rA + 8;
#pragma unroll
        for (int ni = 0; ni < 4; ++ni) {
            int c0 = n0 + n_w + 8 * ni + 2 * tig;
            if (rA < Mloc) {
                Cp[(long long)rA * ldc + c0    ] = acc[mi][ni][0];
                Cp[(long long)rA * ldc + c0 + 1] = acc[mi][ni][1];
            }
            if (rB < Mloc) {
                Cp[(long long)rB * ldc + c0    ] = acc[mi][ni][2];
                Cp[(long long)rB * ldc + c0 + 1] = acc[mi][ni][3];
            }
        }
    }
}

// ---------------- combine: out (already = shared) += sum_k w_k * y[slot_k] ----------------
__global__ void combine_kernel(float* __restrict__ out) {
    int t = blockIdx.x;
    __shared__ int   sslot[TOPK];
    __shared__ float sw[TOPK];
    if (threadIdx.x < TOPK) {
        sslot[threadIdx.x] = g_assign_slot[t * TOPK + threadIdx.x];
        sw[threadIdx.x]    = g_topk_w[t * TOPK + threadIdx.x];
    }
    __syncthreads();
    for (int h = threadIdx.x; h < HDIM; h += 256) {
        float acc = out[(long long)t * HDIM + h];
#pragma unroll
        for (int k = 0; k < TOPK; ++k) {
            int sl = sslot[k];
            if (sl >= 0) acc += sw[k] * g_y[(long long)sl * HDIM + h];
        }
        out[(long long)t * HDIM + h] = acc;
    }
}

// ---------------- launch ----------------
extern "C" void kernel_launch(void* const* d_in, const int* in_sizes, int n_in,
                              void* d_out, int out_size) {
    const float* x     = (const float*)d_in[0];   // hidden_states [512,2048]
    // d_in[1] = residual (unused by reference output)
    const float* gw    = (const float*)d_in[2];   // gate_w [2048,32]
    const float* bias  = (const float*)d_in[3];   // bias [32]
    const float* w13   = (const float*)d_in[4];   // [32,2048,2816]
    const float* w2    = (const float*)d_in[5];   // [32,1408,2048]
    const float* sgu   = (const float*)d_in[6];   // [2048,5632]
    const float* sdn   = (const float*)d_in[7];   // [2816,2048]
    float* out = (float*)d_out;

    // 1) routing
    routing_kernel<<<T, 256>>>(x, gw, bias);
    // 2) capacity ranking
    rank_kernel<<<1, 1024>>>();
    // 3) routed gemm1: gathered X @ w13 (fused silu*up) -> g_h1 [E*CAP, IDIM]
    gemm_fused<true, true, PTR_PARAM, PTR_H1><<<dim3(IDIM / 64, CAP / 128, NE), 256>>>(
        x, HDIM,
        w13, 2 * IDIM, IDIM, (long long)HDIM * 2 * IDIM,
        nullptr, IDIM, (long long)CAP * IDIM,
        CAP, HDIM);
    // 4) routed gemm2: g_h1 @ w2 -> g_y [E*CAP, HDIM]
    gemm_plain<true, PTR_H1, PTR_Y><<<dim3(HDIM / 128, CAP / 128, NE), 256>>>(
        nullptr, IDIM, (long long)CAP * IDIM,
        w2, HDIM, (long long)IDIM * HDIM,
        nullptr, HDIM, (long long)CAP * HDIM,
        CAP, IDIM);
    // 5) shared gemm1: X @ shared_gate_up (fused silu*up) -> g_hs [T, ISH]
    gemm_fused<false, false, PTR_PARAM, PTR_HS><<<dim3(ISH / 64, T / 128, 1), 256>>>(
        x, HDIM,
        sgu, 2 * ISH, ISH, 0ll,
        nullptr, ISH, 0ll,
        T, HDIM);
    // 6) shared gemm2: g_hs @ shared_down -> out [T, HDIM]
    gemm_plain<false, PTR_HS, PTR_PARAM><<<dim3(HDIM / 128, T / 128, 1), 256>>>(
        nullptr, ISH, 0ll,
        sdn, HDIM, 0ll,
        out, HDIM, 0ll,
        T, ISH);
    // 7) combine routed into out
    combine_kernel<<<T, 256>>>(out);
}